// round 11
// baseline (speedup 1.0000x reference)
#include <cuda_runtime.h>
#include <cuda_bf16.h>
#include <math.h>
#include <stdint.h>

// Problem constants
#define BB 8
#define SS 1024
#define DD 512
#define HH 8
#define UU 64
#define FF 2048
#define LN_EPS 1e-3f

// ---------------- scratch (device globals; no allocation allowed) ----------
__device__ float g_xc[BB * SS * DD];                // rna(x)
__device__ float g_qwc[HH * DD * UU];
__device__ float g_kwc[HH * DD * UU];
__device__ float g_vwc[HH * DD * DD];
__device__ float g_lwc[(HH * DD) * DD];
__device__ float g_w1c[DD * FF];
__device__ float g_w2c[FF * DD];
__device__ float g_q[HH * BB * SS * UU];            // [H,B,S,U]
__device__ float g_kT[HH * BB * UU * SS];           // [H,B,U,S]
__device__ float g_v[HH * BB * SS * DD];            // [H,B,S,D]
__device__ float g_scores[(size_t)HH * BB * SS * SS];  // [H,B,S,S]
__device__ float g_concat[BB * SS * (HH * DD)];     // [B,S,H*D]
__device__ float g_tmp[BB * SS * DD];               // mha out, then ff2 out
__device__ float g_h[BB * SS * DD];                 // LN1 output
__device__ float g_hc[BB * SS * DD];                // rna(h)
__device__ float g_ff[BB * SS * FF];                // relu(ff1)

// ---------------- helpers ----------------------------------------------------
__device__ __forceinline__ uint32_t f2tf32(float x) {
    uint32_t y;
    asm("cvt.rna.tf32.f32 %0, %1;" : "=r"(y) : "f"(x));
    return y;
}
__device__ __forceinline__ float rna(float x) { return __uint_as_float(f2tf32(x)); }

__device__ __forceinline__ void mma_tf32(float* c, const uint32_t* a, const uint32_t* b) {
    asm volatile(
        "mma.sync.aligned.m16n8k8.row.col.f32.tf32.tf32.f32 "
        "{%0,%1,%2,%3}, {%4,%5,%6,%7}, {%8,%9}, {%0,%1,%2,%3};\n"
        : "+f"(c[0]), "+f"(c[1]), "+f"(c[2]), "+f"(c[3])
        : "r"(a[0]), "r"(a[1]), "r"(a[2]), "r"(a[3]), "r"(b[0]), "r"(b[1]));
}

__device__ __forceinline__ void ldsm4(uint32_t& r0, uint32_t& r1, uint32_t& r2, uint32_t& r3,
                                      uint32_t addr) {
    asm volatile("ldmatrix.sync.aligned.m8n8.x4.shared.b16 {%0,%1,%2,%3}, [%4];"
                 : "=r"(r0), "=r"(r1), "=r"(r2), "=r"(r3) : "r"(addr));
}

__device__ __forceinline__ uint32_t smem_u32(const void* p) {
    uint32_t a;
    asm("{ .reg .u64 t; cvta.to.shared.u64 t, %1; cvt.u32.u64 %0, t; }" : "=r"(a) : "l"(p));
    return a;
}

// ---------------- tf32 tensor-core batched strided GEMM ---------------------
// C[z][m,n] = alpha * sum_k A[z][m,k]*B[z][k,n] (+bias[n]) (+relu) (+rna)
// Inputs must already be tf32-exact (pre-rounded). A k-contiguous, B n-contiguous,
// M % 128 == 0, K % 16 == 0, sAm % 4 == 0. N guarded.
#define BM 128
#define BN 128
#define BK 16
#define BKP 20   // padded k-stride: 80B rows, 16B-aligned, ldmatrix conflict-free

__global__ __launch_bounds__(128)
void gemm_tc(const float* __restrict__ Af, const float* __restrict__ Bf,
             float* __restrict__ C, const float* __restrict__ bias,
             int M, int N, int K,
             int sAm, int sBk, int sCm, int sCn,
             int HD, int sA1, int sA2, int sB1, int sB2, int sC1, int sC2,
             float alpha, int relu, int rnd)
{
    const int z = blockIdx.z;
    const uint32_t* A = (const uint32_t*)Af + (size_t)(z / HD) * sA1 + (size_t)(z % HD) * sA2;
    const uint32_t* B = (const uint32_t*)Bf + (size_t)(z / HD) * sB1 + (size_t)(z % HD) * sB2;
    C += (size_t)(z / HD) * sC1 + (size_t)(z % HD) * sC2;

    const int row0 = blockIdx.y * BM;
    const int col0 = blockIdx.x * BN;
    const int tid  = threadIdx.x;
    const int w    = tid >> 5;
    const int lane = tid & 31;
    const int wm   = w & 1;          // 2 warps over M (64 rows)
    const int wn   = w >> 1;         // 2 warps over N (64 cols)
    const int r    = lane >> 2;
    const int cq   = lane & 3;

    __shared__ __align__(16) uint32_t As[2][BM][BKP];
    __shared__ __align__(16) uint32_t Bs[2][BN][BKP];

    float acc[4][8][4];
#pragma unroll
    for (int i = 0; i < 4; i++)
#pragma unroll
        for (int j = 0; j < 8; j++)
#pragma unroll
            for (int q = 0; q < 4; q++) acc[i][j][q] = 0.f;

    // ---- ldmatrix per-lane geometry ----
    const int T  = lane >> 3;        // tile index 0..3
    const int ri = lane & 7;         // row within tile
    const int aRowLane = (T & 1) * 8 + ri;
    const int aKadd    = (T >> 1) * 4;
    const int bColLane = (T >> 1) * 8 + ri;
    const int bKadd    = (T & 1) * 4;
    // per-buffer base offsets (bytes) for ldmatrix
    const uint32_t aOffBase = (uint32_t)(wm * 64 + aRowLane) * 80 + (uint32_t)aKadd * 4;
    const uint32_t bOffBase = (uint32_t)(wn * 64 + bColLane) * 80 + (uint32_t)bKadd * 4;

    // ---- loader geometry ----
    const int arow = tid >> 2;            // 0..31 (A rows, 4 blocks of 32)
    const int ak4  = (tid & 3) * 4;       // k offset (x4)
    uint4 a4s[4];
    uint32_t rB[16];
    const int gn  = col0 + tid;
    const bool okn = (gn < N);

    // ---- load tile 0 ----
#pragma unroll
    for (int rr = 0; rr < 4; rr++)
        a4s[rr] = *(const uint4*)&A[(size_t)(row0 + arow + rr * 32) * sAm + ak4];
#pragma unroll
    for (int l = 0; l < 16; l++)
        rB[l] = okn ? B[(size_t)l * sBk + gn] : 0u;

#pragma unroll
    for (int rr = 0; rr < 4; rr++)
        *(uint4*)&As[0][arow + rr * 32][ak4] = a4s[rr];
#pragma unroll
    for (int l4 = 0; l4 < 4; l4++)
        *(uint4*)&Bs[0][tid][l4 * 4] =
            make_uint4(rB[l4 * 4], rB[l4 * 4 + 1], rB[l4 * 4 + 2], rB[l4 * 4 + 3]);
    __syncthreads();

    int cur = 0;
    for (int k0 = 0; k0 < K; k0 += BK) {
        const bool nxt = (k0 + BK) < K;
        if (nxt) {
            const int kn = k0 + BK;
#pragma unroll
            for (int rr = 0; rr < 4; rr++)
                a4s[rr] = *(const uint4*)&A[(size_t)(row0 + arow + rr * 32) * sAm + kn + ak4];
#pragma unroll
            for (int l = 0; l < 16; l++)
                rB[l] = okn ? B[(size_t)(kn + l) * sBk + gn] : 0u;
        }

        // ---- compute from smem buffer `cur` ----
        const uint32_t aBase = smem_u32(&As[cur][0][0]) + aOffBase;
        const uint32_t bBase = smem_u32(&Bs[cur][0][0]) + bOffBase;
#pragma unroll
        for (int k8 = 0; k8 < BK; k8 += 8) {
            uint32_t af[4][4];
            uint32_t bf[8][2];
#pragma unroll
            for (int mt = 0; mt < 4; mt++)
                ldsm4(af[mt][0], af[mt][1], af[mt][2], af[mt][3],
                      aBase + (uint32_t)k8 * 4 + (uint32_t)mt * (16 * 80));
#pragma unroll
            for (int p = 0; p < 4; p++)
                ldsm4(bf[2 * p][0], bf[2 * p][1], bf[2 * p + 1][0], bf[2 * p + 1][1],
                      bBase + (uint32_t)k8 * 4 + (uint32_t)p * (16 * 80));
#pragma unroll
            for (int mt = 0; mt < 4; mt++)
#pragma unroll
                for (int nt = 0; nt < 8; nt++)
                    mma_tf32(acc[mt][nt], af[mt], bf[nt]);
        }

        if (nxt) {
            const int nb = cur ^ 1;
#pragma unroll
            for (int rr = 0; rr < 4; rr++)
                *(uint4*)&As[nb][arow + rr * 32][ak4] = a4s[rr];
#pragma unroll
            for (int l4 = 0; l4 < 4; l4++)
                *(uint4*)&Bs[nb][tid][l4 * 4] =
                    make_uint4(rB[l4 * 4], rB[l4 * 4 + 1], rB[l4 * 4 + 2], rB[l4 * 4 + 3]);
            cur = nb;
            __syncthreads();
        }
    }

    // ---- epilogue ----
#pragma unroll
    for (int mt = 0; mt < 4; mt++) {
        const int rr0 = row0 + wm * 64 + mt * 16 + r;
        const int rr1 = rr0 + 8;
#pragma unroll
        for (int nt = 0; nt < 8; nt++) {
            const int cc0 = col0 + wn * 64 + nt * 8 + 2 * cq;
            const int cc1 = cc0 + 1;
            if (cc0 < N) {
                float v0 = acc[mt][nt][0] * alpha;
                float v2 = acc[mt][nt][2] * alpha;
                if (bias) { v0 += bias[cc0]; v2 += bias[cc0]; }
                if (relu) { v0 = fmaxf(v0, 0.f); v2 = fmaxf(v2, 0.f); }
                if (rnd)  { v0 = rna(v0); v2 = rna(v2); }
                C[(size_t)rr0 * sCm + (size_t)cc0 * sCn] = v0;
                C[(size_t)rr1 * sCm + (size_t)cc0 * sCn] = v2;
            }
            if (cc1 < N) {
                float v1 = acc[mt][nt][1] * alpha;
                float v3 = acc[mt][nt][3] * alpha;
                if (bias) { v1 += bias[cc1]; v3 += bias[cc1]; }
                if (relu) { v1 = fmaxf(v1, 0.f); v3 = fmaxf(v3, 0.f); }
                if (rnd)  { v1 = rna(v1); v3 = rna(v3); }
                C[(size_t)rr0 * sCm + (size_t)cc1 * sCn] = v1;
                C[(size_t)rr1 * sCm + (size_t)cc1 * sCn] = v3;
            }
        }
    }
}

// ---------------- elementwise tf32 rounding ---------------------------------
__global__ __launch_bounds__(1024)
void rna_copy(const float* __restrict__ in, float* __restrict__ out)
{
    const int i = blockIdx.x * 1024 + threadIdx.x;
    out[i] = rna(in[i]);
}

// ---------------- softmax over rows of length 1024 (rounds output) ----------
__global__ __launch_bounds__(256)
void softmax_k(float* __restrict__ S)
{
    float4* p = (float4*)(S + (size_t)blockIdx.x * 1024);
    const int t = threadIdx.x;
    const int lane = t & 31, wid = t >> 5;
    __shared__ float red[8];

    float4 v = p[t];
    float m = fmaxf(fmaxf(v.x, v.y), fmaxf(v.z, v.w));
#pragma unroll
    for (int s = 16; s > 0; s >>= 1) m = fmaxf(m, __shfl_xor_sync(0xffffffffu, m, s));
    if (lane == 0) red[wid] = m;
    __syncthreads();
    m = red[lane & 7];
#pragma unroll
    for (int s = 4; s > 0; s >>= 1) m = fmaxf(m, __shfl_xor_sync(0xffffffffu, m, s));
    m = __shfl_sync(0xffffffffu, m, 0);

    v.x = __expf(v.x - m); v.y = __expf(v.y - m);
    v.z = __expf(v.z - m); v.w = __expf(v.w - m);
    float sum = v.x + v.y + v.z + v.w;
#pragma unroll
    for (int s = 16; s > 0; s >>= 1) sum += __shfl_xor_sync(0xffffffffu, sum, s);
    __syncthreads();
    if (lane == 0) red[wid] = sum;
    __syncthreads();
    sum = red[lane & 7];
#pragma unroll
    for (int s = 4; s > 0; s >>= 1) sum += __shfl_xor_sync(0xffffffffu, sum, s);
    sum = __shfl_sync(0xffffffffu, sum, 0);

    float inv = 1.f / sum;
    v.x = rna(v.x * inv); v.y = rna(v.y * inv);
    v.z = rna(v.z * inv); v.w = rna(v.w * inv);
    p[t] = v;
}

// ---------------- residual + layernorm (rows of 512) ------------------------
__global__ __launch_bounds__(256)
void ln_k(float* __restrict__ out, float* __restrict__ outr,
          const float* __restrict__ a, const float* __restrict__ b,
          const float* __restrict__ gamma, const float* __restrict__ beta)
{
    size_t base = (size_t)blockIdx.x * DD;
    int t = threadIdx.x;
    float x0 = a[base + t]       + b[base + t];
    float x1 = a[base + t + 256] + b[base + t + 256];

    __shared__ float r1[256], r2[256];
    r1[t] = x0 + x1;
    r2[t] = x0 * x0 + x1 * x1;
    __syncthreads();
    for (int s = 128; s > 0; s >>= 1) {
        if (t < s) { r1[t] += r1[t + s]; r2[t] += r2[t + s]; }
        __syncthreads();
    }
    float mean = r1[0] * (1.f / DD);
    float var  = r2[0] * (1.f / DD) - mean * mean;
    float rstd = rsqrtf(var + LN_EPS);

    float y0 = gamma[t]       * (x0 - mean) * rstd + beta[t];
    float y1 = gamma[t + 256] * (x1 - mean) * rstd + beta[t + 256];
    out[base + t]       = y0;
    out[base + t + 256] = y1;
    if (outr) {
        outr[base + t]       = rna(y0);
        outr[base + t + 256] = rna(y1);
    }
}

// ---------------- host side --------------------------------------------------
static void gemm(const float* A, const float* B, float* C, const float* bias,
                 int M, int N, int K, int nb, int HD,
                 int sAm, int sBk, int sCm, int sCn,
                 int sA1, int sA2, int sB1, int sB2, int sC1, int sC2,
                 float alpha, int relu, int rnd)
{
    dim3 grid((N + BN - 1) / BN, (M + BM - 1) / BM, nb);
    gemm_tc<<<grid, 128>>>(A, B, C, bias, M, N, K,
                           sAm, sBk, sCm, sCn,
                           HD, sA1, sA2, sB1, sB2, sC1, sC2, alpha, relu, rnd);
}

extern "C" void kernel_launch(void* const* d_in, const int* in_sizes, int n_in,
                              void* d_out, int out_size)
{
    const float* x      = (const float*)d_in[0];
    const float* qw     = (const float*)d_in[1];
    const float* kw     = (const float*)d_in[2];
    const float* vw     = (const float*)d_in[3];
    const float* lw     = (const float*)d_in[4];
    const float* gamma1 = (const float*)d_in[5];
    const float* beta1  = (const float*)d_in[6];
    const float* w1     = (const float*)d_in[7];
    const float* b1     = (const float*)d_in[8];
    const float* w2     = (const float*)d_in[9];
    const float* b2     = (const float*)d_in[10];
    const float* gamma2 = (const float*)d_in[11];
    const float* beta2  = (const float*)d_in[12];
    float* out = (float*)d_out;

    float *xc, *qwc, *kwc, *vwc, *lwc, *w1c, *w2c;
    float *q, *kT, *v, *scores, *concat, *tmp, *h, *hc, *ff;
    cudaGetSymbolAddress((void**)&xc,  g_xc);
    cudaGetSymbolAddress((void**)&qwc, g_qwc);
    cudaGetSymbolAddress((void**)&kwc, g_kwc);
    cudaGetSymbolAddress((void**)&vwc, g_vwc);
    cudaGetSymbolAddress((void**)&lwc, g_lwc);
    cudaGetSymbolAddress((void**)&w1c, g_w1c);
    cudaGetSymbolAddress((void**)&w2c, g_w2c);
    cudaGetSymbolAddress((void**)&q,      g_q);
    cudaGetSymbolAddress((void**)&kT,     g_kT);
    cudaGetSymbolAddress((void**)&v,      g_v);
    cudaGetSymbolAddress((void**)&scores, g_scores);
    cudaGetSymbolAddress((void**)&concat, g_concat);
    cudaGetSymbolAddress((void**)&tmp,    g_tmp);
    cudaGetSymbolAddress((void**)&h,      g_h);
    cudaGetSymbolAddress((void**)&hc,     g_hc);
    cudaGetSymbolAddress((void**)&ff,     g_ff);

    const float scale = 1.0f / sqrtf((float)DD);

    // ---- pre-round inputs to tf32-exact values ----
    rna_copy<<<(BB * SS * DD) / 1024, 1024>>>(x, xc);
    rna_copy<<<(HH * DD * UU) / 1024, 1024>>>(qw, qwc);
    rna_copy<<<(HH * DD * UU) / 1024, 1024>>>(kw, kwc);
    rna_copy<<<(HH * DD * DD) / 1024, 1024>>>(vw, vwc);
    rna_copy<<<(HH * DD * DD) / 1024, 1024>>>(lw, lwc);
    rna_copy<<<(DD * FF) / 1024, 1024>>>(w1, w1c);
    rna_copy<<<(FF * DD) / 1024, 1024>>>(w2, w2c);

    // batches z = h*B + b, HD = B: z/HD = head, z%HD = batch
    // 1) Q projection: [S,U] per (h,b)  (output rounded)
    gemm(xc, qwc, q, nullptr, SS, UU, DD, HH * BB, BB,
         DD, UU, UU, 1,
         0, SS * DD,
         DD * UU, 0,
         BB * SS * UU, SS * UU,
         1.f, 0, 1);

    // 2) K projection stored transposed: kT[h,b][u,s]  (output rounded)
    gemm(xc, kwc, kT, nullptr, SS, UU, DD, HH * BB, BB,
         DD, UU, 1, SS,
         0, SS * DD,
         DD * UU, 0,
         BB * UU * SS, UU * SS,
         1.f, 0, 1);

    // 3) V projection: [S,D] per (h,b)  (output rounded)
    gemm(xc, vwc, v, nullptr, SS, DD, DD, HH * BB, BB,
         DD, DD, DD, 1,
         0, SS * DD,
         DD * DD, 0,
         BB * SS * DD, SS * DD,
         1.f, 0, 1);

    // 4) scores = scale * Q @ K^T : [S,S] per (h,b)
    gemm(q, kT, scores, nullptr, SS, SS, UU, HH * BB, BB,
         UU, SS, SS, 1,
         BB * SS * UU, SS * UU,
         BB * UU * SS, UU * SS,
         BB * SS * SS, SS * SS,
         scale, 0, 0);

    // 5) softmax rows (rounds output)
    softmax_k<<<HH * BB * SS, 256>>>(scores);

    // 6) attn = probs @ V -> concat layout [B,S,H*D]  (output rounded)
    gemm(scores, v, concat, nullptr, SS, DD, SS, HH * BB, BB,
         SS, DD, HH * DD, 1,
         BB * SS * SS, SS * SS,
         BB * SS * DD, SS * DD,
         DD, SS * HH * DD,
         1.f, 0, 1);

    // 7) output projection: [B*S, 4096] @ [4096, 512]
    gemm(concat, lwc, tmp, nullptr, BB * SS, DD, HH * DD, 1, 1,
         HH * DD, DD, DD, 1,
         0, 0, 0, 0, 0, 0,
         1.f, 0, 0);

    // 8) h = LN(x + mha); hc = rna(h)
    ln_k<<<BB * SS, 256>>>(h, hc, x, tmp, gamma1, beta1);

    // 9) ff = rna(relu(hc @ w1 + b1))
    gemm(hc, w1c, ff, b1, BB * SS, FF, DD, 1, 1,
         DD, FF, FF, 1,
         0, 0, 0, 0, 0, 0,
         1.f, 1, 1);

    // 10) tmp = ff @ w2 + b2
    gemm(ff, w2c, tmp, b2, BB * SS, DD, FF, 1, 1,
         FF, DD, DD, 1,
         0, 0, 0, 0, 0, 0,
         1.f, 0, 0);

    // 11) out = LN(h + tmp)
    ln_k<<<BB * SS, 256>>>(out, nullptr, h, tmp, gamma2, beta2);
}

// round 12
// speedup vs baseline: 1.1188x; 1.1188x over previous
#include <cuda_runtime.h>
#include <cuda_bf16.h>
#include <math.h>
#include <stdint.h>

// Problem constants
#define BB 8
#define SS 1024
#define DD 512
#define HH 8
#define UU 64
#define FF 2048
#define LN_EPS 1e-3f
#define SCALE 0.04419417382415922f   // 1/sqrt(512)

// ---------------- scratch (device globals; no allocation allowed) ----------
__device__ float g_qwT[HH * UU * DD];               // [h][u][d]
__device__ float g_kwT[HH * UU * DD];
__device__ float g_vwT[HH * DD * DD];               // [h][e][d]
__device__ float g_lwT[DD * (HH * DD)];             // [d][4096]
__device__ float g_w1T[FF * DD];                    // [f][d]
__device__ float g_w2T[DD * FF];                    // [d][f]
__device__ float g_q[HH * BB * SS * UU];            // [z][s][u]
__device__ float g_k[HH * BB * SS * UU];            // [z][s][u]
__device__ float g_v[HH * BB * DD * SS];            // V^T: [z][e][s]
__device__ float g_scores[(size_t)HH * BB * SS * SS];  // [z][s][t]
__device__ float g_concat[BB * SS * (HH * DD)];     // [B,S,H*D]
__device__ float g_tmp[BB * SS * DD];
__device__ float g_h[BB * SS * DD];
__device__ float g_ff[BB * SS * FF];

// ---------------- helpers ----------------------------------------------------
__device__ __forceinline__ void mma_tf32(float* c, const uint32_t* a, const uint32_t* b) {
    asm volatile(
        "mma.sync.aligned.m16n8k8.row.col.f32.tf32.tf32.f32 "
        "{%0,%1,%2,%3}, {%4,%5,%6,%7}, {%8,%9}, {%0,%1,%2,%3};\n"
        : "+f"(c[0]), "+f"(c[1]), "+f"(c[2]), "+f"(c[3])
        : "r"(a[0]), "r"(a[1]), "r"(a[2]), "r"(a[3]), "r"(b[0]), "r"(b[1]));
}

__device__ __forceinline__ void ldsm4(uint32_t& r0, uint32_t& r1, uint32_t& r2, uint32_t& r3,
                                      uint32_t addr) {
    asm volatile("ldmatrix.sync.aligned.m8n8.x4.shared.b16 {%0,%1,%2,%3}, [%4];"
                 : "=r"(r0), "=r"(r1), "=r"(r2), "=r"(r3) : "r"(addr));
}

__device__ __forceinline__ uint32_t smem_u32(const void* p) {
    uint32_t a;
    asm("{ .reg .u64 t; cvta.to.shared.u64 t, %1; cvt.u32.u64 %0, t; }" : "=r"(a) : "l"(p));
    return a;
}

__device__ __forceinline__ void cp16(uint32_t saddr, const void* g) {
    asm volatile("cp.async.cg.shared.global [%0], [%1], 16;\n" :: "r"(saddr), "l"(g));
}
__device__ __forceinline__ void cp_commit() { asm volatile("cp.async.commit_group;\n"); }
template <int Nn>
__device__ __forceinline__ void cp_wait() { asm volatile("cp.async.wait_group %0;\n" :: "n"(Nn)); }

// ---------------- tf32 tensor-core batched K-major GEMM ----------------------
// C[z][m,n] = alpha * sum_k A[z][m,k]*B[z][n,k] (+bias[n]) (+relu)
// A: [M,K] k-contig (row stride sAm), B: [N,K] k-contig (row stride sBn).
// M % 128 == 0, K % 16 == 0, sAm/sBn % 4 == 0. N guarded on epilogue/loads.
#define BM 128
#define BN 128
#define BK 16
#define NSTAGE 4
#define ROWPB 80            // 20 floats per smem row
#define BOFF  (128 * 80)    // B tile offset within a stage (10240 B)
#define STAGEB (256 * 80)   // one stage = A(10240) + B(10240)

__global__ __launch_bounds__(128)
void gemm_tc(const float* __restrict__ Af, const float* __restrict__ Bf,
             float* __restrict__ C, const float* __restrict__ bias,
             int M, int N, int K, int sAm, int sBn, int sCm,
             int HD, int sA1, int sA2, int sB1, int sB2, int sC1, int sC2,
             float alpha, int relu)
{
    extern __shared__ __align__(16) uint8_t smem[];

    const int z = blockIdx.z;
    const float* A = Af + (size_t)(z / HD) * sA1 + (size_t)(z % HD) * sA2;
    const float* B = Bf + (size_t)(z / HD) * sB1 + (size_t)(z % HD) * sB2;
    C += (size_t)(z / HD) * sC1 + (size_t)(z % HD) * sC2;

    const int row0 = blockIdx.y * BM;
    const int col0 = blockIdx.x * BN;
    const int tid  = threadIdx.x;
    const int w    = tid >> 5;
    const int lane = tid & 31;
    const int wm   = w & 1;          // 2 warps over M (64 rows)
    const int wn   = w >> 1;         // 2 warps over N (64 cols)
    const int r    = lane >> 2;
    const int cq   = lane & 3;

    float acc[4][8][4];
#pragma unroll
    for (int i = 0; i < 4; i++)
#pragma unroll
        for (int j = 0; j < 8; j++)
#pragma unroll
            for (int q = 0; q < 4; q++) acc[i][j][q] = 0.f;

    // ---- ldmatrix per-lane geometry (identical to round-9 mapping) ----
    const int T  = lane >> 3;
    const int ri = lane & 7;
    const uint32_t sb = smem_u32(smem);
    const uint32_t aOff = (uint32_t)(wm * 64 + (T & 1) * 8 + ri) * ROWPB + (uint32_t)((T >> 1) * 4) * 4;
    const uint32_t bOff = BOFF + (uint32_t)(wn * 64 + (T >> 1) * 8 + ri) * ROWPB + (uint32_t)((T & 1) * 4) * 4;
    uint32_t aB[NSTAGE], bB[NSTAGE];
#pragma unroll
    for (int s = 0; s < NSTAGE; s++) {
        aB[s] = sb + s * STAGEB + aOff;
        bB[s] = sb + s * STAGEB + bOff;
    }

    // ---- loader geometry: thread tid owns A row tid and B row tid ----
    const float* aSrc = A + (size_t)(row0 + tid) * sAm;
    const int bRow = (col0 + tid < N) ? (col0 + tid) : (N - 1);
    const float* bSrc = B + (size_t)bRow * sBn;
    const uint32_t aDst = sb + (uint32_t)tid * ROWPB;
    const uint32_t bDst = sb + BOFF + (uint32_t)tid * ROWPB;

    const int nt = K / BK;

    // prologue: stages 0..NSTAGE-2
#pragma unroll
    for (int s = 0; s < NSTAGE - 1; s++) {
        if (s < nt) {
            const float* as = aSrc + s * BK;
            const float* bs = bSrc + s * BK;
            const uint32_t ad = aDst + s * STAGEB;
            const uint32_t bd = bDst + s * STAGEB;
#pragma unroll
            for (int c = 0; c < 4; c++) cp16(ad + c * 16, as + c * 4);
#pragma unroll
            for (int c = 0; c < 4; c++) cp16(bd + c * 16, bs + c * 4);
        }
        cp_commit();
    }

    for (int t = 0; t < nt; t++) {
        cp_wait<NSTAGE - 2>();
        __syncthreads();

        // issue loads for tile t+NSTAGE-1 into stage (t+NSTAGE-1)%NSTAGE
        const int tl = t + NSTAGE - 1;
        if (tl < nt) {
            const int s = tl & (NSTAGE - 1);
            const float* as = aSrc + tl * BK;
            const float* bs = bSrc + tl * BK;
            const uint32_t ad = aDst + s * STAGEB;
            const uint32_t bd = bDst + s * STAGEB;
#pragma unroll
            for (int c = 0; c < 4; c++) cp16(ad + c * 16, as + c * 4);
#pragma unroll
            for (int c = 0; c < 4; c++) cp16(bd + c * 16, bs + c * 4);
        }
        cp_commit();

        // ---- compute on stage t%NSTAGE ----
        const int s = t & (NSTAGE - 1);
#pragma unroll
        for (int k8 = 0; k8 < BK; k8 += 8) {
            uint32_t af[4][4];
            uint32_t bf[8][2];
#pragma unroll
            for (int mt = 0; mt < 4; mt++)
                ldsm4(af[mt][0], af[mt][1], af[mt][2], af[mt][3],
                      aB[s] + (uint32_t)k8 * 4 + (uint32_t)mt * (16 * ROWPB));
#pragma unroll
            for (int p = 0; p < 4; p++)
                ldsm4(bf[2 * p][0], bf[2 * p][1], bf[2 * p + 1][0], bf[2 * p + 1][1],
                      bB[s] + (uint32_t)k8 * 4 + (uint32_t)p * (16 * ROWPB));
#pragma unroll
            for (int mt = 0; mt < 4; mt++)
#pragma unroll
                for (int nt8 = 0; nt8 < 8; nt8++)
                    mma_tf32(acc[mt][nt8], af[mt], bf[nt8]);
        }
    }

    // ---- epilogue (sCn == 1) ----
#pragma unroll
    for (int mt = 0; mt < 4; mt++) {
        const int rr0 = row0 + wm * 64 + mt * 16 + r;
        const int rr1 = rr0 + 8;
#pragma unroll
        for (int nt8 = 0; nt8 < 8; nt8++) {
            const int cc0 = col0 + wn * 64 + nt8 * 8 + 2 * cq;
            const int cc1 = cc0 + 1;
            if (cc0 < N) {
                float v0 = acc[mt][nt8][0] * alpha;
                float v2 = acc[mt][nt8][2] * alpha;
                if (bias) { v0 += bias[cc0]; v2 += bias[cc0]; }
                if (relu) { v0 = fmaxf(v0, 0.f); v2 = fmaxf(v2, 0.f); }
                C[(size_t)rr0 * sCm + cc0] = v0;
                C[(size_t)rr1 * sCm + cc0] = v2;
            }
            if (cc1 < N) {
                float v1 = acc[mt][nt8][1] * alpha;
                float v3 = acc[mt][nt8][3] * alpha;
                if (bias) { v1 += bias[cc1]; v3 += bias[cc1]; }
                if (relu) { v1 = fmaxf(v1, 0.f); v3 = fmaxf(v3, 0.f); }
                C[(size_t)rr0 * sCm + cc1] = v1;
                C[(size_t)rr1 * sCm + cc1] = v3;
            }
        }
    }
}

// ---------------- batched transpose [R,C] -> [C,R] ---------------------------
__global__ void transpose_k(const float* __restrict__ in, float* __restrict__ out,
                            int R, int Cc)
{
    __shared__ float t[32][33];
    const size_t bo = (size_t)blockIdx.z * R * Cc;
    const int r0 = blockIdx.y * 32, c0 = blockIdx.x * 32;
    const int tx = threadIdx.x, ty = threadIdx.y;
#pragma unroll
    for (int i = 0; i < 4; i++)
        t[ty + 8 * i][tx] = in[bo + (size_t)(r0 + ty + 8 * i) * Cc + c0 + tx];
    __syncthreads();
#pragma unroll
    for (int i = 0; i < 4; i++)
        out[bo + (size_t)(c0 + ty + 8 * i) * R + r0 + tx] = t[tx][ty + 8 * i];
}

// ---------------- softmax over rows of length 1024 ---------------------------
__global__ __launch_bounds__(256)
void softmax_k(float* __restrict__ S)
{
    float4* p = (float4*)(S + (size_t)blockIdx.x * 1024);
    const int t = threadIdx.x;
    const int lane = t & 31, wid = t >> 5;
    __shared__ float red[8];

    float4 v = p[t];
    float m = fmaxf(fmaxf(v.x, v.y), fmaxf(v.z, v.w));
#pragma unroll
    for (int s = 16; s > 0; s >>= 1) m = fmaxf(m, __shfl_xor_sync(0xffffffffu, m, s));
    if (lane == 0) red[wid] = m;
    __syncthreads();
    m = red[lane & 7];
#pragma unroll
    for (int s = 4; s > 0; s >>= 1) m = fmaxf(m, __shfl_xor_sync(0xffffffffu, m, s));
    m = __shfl_sync(0xffffffffu, m, 0);

    v.x = __expf(v.x - m); v.y = __expf(v.y - m);
    v.z = __expf(v.z - m); v.w = __expf(v.w - m);
    float sum = v.x + v.y + v.z + v.w;
#pragma unroll
    for (int s = 16; s > 0; s >>= 1) sum += __shfl_xor_sync(0xffffffffu, sum, s);
    __syncthreads();
    if (lane == 0) red[wid] = sum;
    __syncthreads();
    sum = red[lane & 7];
#pragma unroll
    for (int s = 4; s > 0; s >>= 1) sum += __shfl_xor_sync(0xffffffffu, sum, s);
    sum = __shfl_sync(0xffffffffu, sum, 0);

    float inv = 1.f / sum;
    v.x *= inv; v.y *= inv; v.z *= inv; v.w *= inv;
    p[t] = v;
}

// ---------------- residual + layernorm (rows of 512) ------------------------
__global__ __launch_bounds__(256)
void ln_k(float* __restrict__ out, const float* __restrict__ a,
          const float* __restrict__ b, const float* __restrict__ gamma,
          const float* __restrict__ beta)
{
    size_t base = (size_t)blockIdx.x * DD;
    int t = threadIdx.x;
    float x0 = a[base + t]       + b[base + t];
    float x1 = a[base + t + 256] + b[base + t + 256];

    __shared__ float r1[256], r2[256];
    r1[t] = x0 + x1;
    r2[t] = x0 * x0 + x1 * x1;
    __syncthreads();
    for (int s = 128; s > 0; s >>= 1) {
        if (t < s) { r1[t] += r1[t + s]; r2[t] += r2[t + s]; }
        __syncthreads();
    }
    float mean = r1[0] * (1.f / DD);
    float var  = r2[0] * (1.f / DD) - mean * mean;
    float rstd = rsqrtf(var + LN_EPS);

    out[base + t]       = gamma[t]       * (x0 - mean) * rstd + beta[t];
    out[base + t + 256] = gamma[t + 256] * (x1 - mean) * rstd + beta[t + 256];
}

// ---------------- host side --------------------------------------------------
#define GEMM_SMEM (NSTAGE * STAGEB)

static void gemm(const float* A, const float* B, float* C, const float* bias,
                 int M, int N, int K, int nb, int HD,
                 int sAm, int sBn, int sCm,
                 int sA1, int sA2, int sB1, int sB2, int sC1, int sC2,
                 float alpha, int relu)
{
    dim3 grid((N + BN - 1) / BN, M / BM, nb);
    gemm_tc<<<grid, 128, GEMM_SMEM>>>(A, B, C, bias, M, N, K, sAm, sBn, sCm,
                                      HD, sA1, sA2, sB1, sB2, sC1, sC2, alpha, relu);
}

extern "C" void kernel_launch(void* const* d_in, const int* in_sizes, int n_in,
                              void* d_out, int out_size)
{
    const float* x      = (const float*)d_in[0];
    const float* qw     = (const float*)d_in[1];
    const float* kw     = (const float*)d_in[2];
    const float* vw     = (const float*)d_in[3];
    const float* lw     = (const float*)d_in[4];
    const float* gamma1 = (const float*)d_in[5];
    const float* beta1  = (const float*)d_in[6];
    const float* w1     = (const float*)d_in[7];
    const float* b1     = (const float*)d_in[8];
    const float* w2     = (const float*)d_in[9];
    const float* b2     = (const float*)d_in[10];
    const float* gamma2 = (const float*)d_in[11];
    const float* beta2  = (const float*)d_in[12];
    float* out = (float*)d_out;

    float *qwT, *kwT, *vwT, *lwT, *w1T, *w2T;
    float *q, *k, *v, *scores, *concat, *tmp, *h, *ff;
    cudaGetSymbolAddress((void**)&qwT, g_qwT);
    cudaGetSymbolAddress((void**)&kwT, g_kwT);
    cudaGetSymbolAddress((void**)&vwT, g_vwT);
    cudaGetSymbolAddress((void**)&lwT, g_lwT);
    cudaGetSymbolAddress((void**)&w1T, g_w1T);
    cudaGetSymbolAddress((void**)&w2T, g_w2T);
    cudaGetSymbolAddress((void**)&q,      g_q);
    cudaGetSymbolAddress((void**)&k,      g_k);
    cudaGetSymbolAddress((void**)&v,      g_v);
    cudaGetSymbolAddress((void**)&scores, g_scores);
    cudaGetSymbolAddress((void**)&concat, g_concat);
    cudaGetSymbolAddress((void**)&tmp,    g_tmp);
    cudaGetSymbolAddress((void**)&h,      g_h);
    cudaGetSymbolAddress((void**)&ff,     g_ff);

    cudaFuncSetAttribute(gemm_tc, cudaFuncAttributeMaxDynamicSharedMemorySize, GEMM_SMEM);

    // ---- transpose constant weights to K-major ----
    transpose_k<<<dim3(2, 16, 8),   dim3(32, 8)>>>(qw, qwT, DD, UU);
    transpose_k<<<dim3(2, 16, 8),   dim3(32, 8)>>>(kw, kwT, DD, UU);
    transpose_k<<<dim3(16, 16, 8),  dim3(32, 8)>>>(vw, vwT, DD, DD);
    transpose_k<<<dim3(16, 128, 1), dim3(32, 8)>>>(lw, lwT, HH * DD, DD);
    transpose_k<<<dim3(64, 16, 1),  dim3(32, 8)>>>(w1, w1T, DD, FF);
    transpose_k<<<dim3(16, 64, 1),  dim3(32, 8)>>>(w2, w2T, FF, DD);

    // z = h*BB + b (HD = BB)
    // 1) Q[z][s][u] = sum_d x[b][s][d] * qwT[h][u][d]
    gemm(x, qwT, q, nullptr, SS, UU, DD, HH * BB, BB,
         DD, DD, UU,
         0, SS * DD,
         UU * DD, 0,
         BB * SS * UU, SS * UU,
         1.f, 0);

    // 2) K[z][s][u] likewise
    gemm(x, kwT, k, nullptr, SS, UU, DD, HH * BB, BB,
         DD, DD, UU,
         0, SS * DD,
         UU * DD, 0,
         BB * SS * UU, SS * UU,
         1.f, 0);

    // 3) V^T[z][e][s] = sum_d vwT[h][e][d] * x[b][s][d]   (M=512, N=1024)
    gemm(vwT, x, v, nullptr, DD, SS, DD, HH * BB, BB,
         DD, DD, SS,
         DD * DD, 0,
         0, SS * DD,
         BB * DD * SS, DD * SS,
         1.f, 0);

    // 4) scores[z][s][t] = scale * sum_u Q[z][s][u] K[z][t][u]   (K=64)
    gemm(q, k, scores, nullptr, SS, SS, UU, HH * BB, BB,
         UU, UU, SS,
         BB * SS * UU, SS * UU,
         BB * SS * UU, SS * UU,
         BB * SS * SS, SS * SS,
         SCALE, 0);

    // 5) softmax rows
    softmax_k<<<HH * BB * SS, 256>>>(scores);

    // 6) attn[z][s][e] = sum_t P[z][s][t] V^T[z][e][t] -> concat [B,S,H*D]
    gemm(scores, v, concat, nullptr, SS, DD, SS, HH * BB, BB,
         SS, SS, HH * DD,
         BB * SS * SS, SS * SS,
         BB * DD * SS, DD * SS,
         DD, SS * HH * DD,
         1.f, 0);

    // 7) output projection: tmp[s][d] = sum_k concat[s][k] lwT[d][k]  (K=4096)
    gemm(concat, lwT, tmp, nullptr, BB * SS, DD, HH * DD, 1, 1,
         HH * DD, HH * DD, DD,
         0, 0, 0, 0, 0, 0,
         1.f, 0);

    // 8) h = LN(x + mha)
    ln_k<<<BB * SS, 256>>>(h, x, tmp, gamma1, beta1);

    // 9) ff = relu(h @ w1 + b1): ff[s][f] = sum_d h[s][d] w1T[f][d]
    gemm(h, w1T, ff, b1, BB * SS, FF, DD, 1, 1,
         DD, DD, FF,
         0, 0, 0, 0, 0, 0,
         1.f, 1);

    // 10) tmp = ff @ w2 + b2: tmp[s][d] = sum_f ff[s][f] w2T[d][f]
    gemm(ff, w2T, tmp, b2, BB * SS, DD, FF, 1, 1,
         FF, FF, DD,
         0, 0, 0, 0, 0, 0,
         1.f, 0);

    // 11) out = LN(h + tmp)
    ln_k<<<BB * SS, 256>>>(out, h, tmp, gamma2, beta2);
}

// round 15
// speedup vs baseline: 1.8055x; 1.6138x over previous
#include <cuda_runtime.h>
#include <cuda_fp16.h>
#include <math.h>
#include <stdint.h>

// Problem constants
#define BB 8
#define SS 1024
#define DD 512
#define HH 8
#define UU 64
#define FF 2048
#define LN_EPS 1e-3f
#define SCALE 0.04419417382415922f   // 1/sqrt(512)

// ---------------- scratch (device globals, 16B-aligned via uint4) -----------
#define U4(n) ((n) / 8)
__device__ uint4 g_xh [U4(BB * SS * DD)];            // half x, [b][s][d]
__device__ uint4 g_qwT[U4(HH * UU * DD)];            // half, [h][u][d]
__device__ uint4 g_kwT[U4(HH * UU * DD)];
__device__ uint4 g_vwT[U4(HH * DD * DD)];            // half, [h][e][d]
__device__ uint4 g_lwT[U4(DD * HH * DD)];            // half, [d][4096]
__device__ uint4 g_w1T[U4(FF * DD)];                 // half, [f][d]
__device__ uint4 g_w2T[U4(DD * FF)];                 // half, [d][f]
__device__ uint4 g_qh [U4(HH * BB * SS * UU)];       // half, [z][s][u]
__device__ uint4 g_kh [U4(HH * BB * SS * UU)];
__device__ uint4 g_vh [U4((size_t)HH * BB * DD * SS)];   // half V^T, [z][e][s]
__device__ uint4 g_sch[U4((size_t)HH * BB * SS * SS)];   // half scores/probs
__device__ uint4 g_cth[U4((size_t)BB * SS * HH * DD)];   // half concat
__device__ uint4 g_hh [U4(BB * SS * DD)];            // half LN1 out
__device__ uint4 g_ffh[U4(BB * SS * FF)];            // half relu(ff1)
__device__ float g_tmp[BB * SS * DD];
__device__ float g_h  [BB * SS * DD];

// ---------------- helpers ----------------------------------------------------
__device__ __forceinline__ void mma_f16(float* c, const uint32_t* a, const uint32_t* b) {
    asm volatile(
        "mma.sync.aligned.m16n8k16.row.col.f32.f16.f16.f32 "
        "{%0,%1,%2,%3}, {%4,%5,%6,%7}, {%8,%9}, {%0,%1,%2,%3};\n"
        : "+f"(c[0]), "+f"(c[1]), "+f"(c[2]), "+f"(c[3])
        : "r"(a[0]), "r"(a[1]), "r"(a[2]), "r"(a[3]), "r"(b[0]), "r"(b[1]));
}

__device__ __forceinline__ void ldsm4(uint32_t& r0, uint32_t& r1, uint32_t& r2, uint32_t& r3,
                                      uint32_t addr) {
    asm volatile("ldmatrix.sync.aligned.m8n8.x4.shared.b16 {%0,%1,%2,%3}, [%4];"
                 : "=r"(r0), "=r"(r1), "=r"(r2), "=r"(r3) : "r"(addr));
}

__device__ __forceinline__ uint32_t smem_u32(const void* p) {
    uint32_t a;
    asm("{ .reg .u64 t; cvta.to.shared.u64 t, %1; cvt.u32.u64 %0, t; }" : "=r"(a) : "l"(p));
    return a;
}

// ---------------- fp16 tensor-core batched K-major GEMM ----------------------
// C[z][m,n] = alpha * sum_k A[z][m,k]*B[z][n,k] (+bias[n]) (+relu)
// A: [M,K] half, k-contig, row stride sAm (halfs, %8==0). B: [N,K] half likewise.
// M % 128 == 0, K % 32 == 0. N guarded. C: half (cHalf) or float, row stride sCm.
#define BM 128
#define BN 128
#define BKH 32          // k per tile (halfs)
#define PITCH 80        // bytes per smem row (64 data + 16 pad)
#define BOFFB (128 * PITCH)   // B tile offset in a buffer (10240 B)

__global__ __launch_bounds__(128)
void gemm_h(const __half* __restrict__ A, const __half* __restrict__ B,
            void* __restrict__ Cv, int cHalf, const float* __restrict__ bias,
            int M, int N, int K, int sAm, int sBn, int sCm,
            int HD, long long sA1, long long sA2, long long sB1, long long sB2,
            long long sC1, long long sC2, float alpha, int relu)
{
    __shared__ __align__(16) uint8_t smem[2][2 * BOFFB];

    const int z = blockIdx.z;
    A += (long long)(z / HD) * sA1 + (long long)(z % HD) * sA2;
    B += (long long)(z / HD) * sB1 + (long long)(z % HD) * sB2;
    const long long cOff = (long long)(z / HD) * sC1 + (long long)(z % HD) * sC2;
    float*  Cf = (float*)Cv + cOff;
    __half* Ch = (__half*)Cv + cOff;

    const int row0 = blockIdx.y * BM;
    const int col0 = blockIdx.x * BN;
    const int tid  = threadIdx.x;
    const int w    = tid >> 5;
    const int lane = tid & 31;
    const int wm   = w & 1;          // 2 warps over M (64 rows)
    const int wn   = w >> 1;         // 2 warps over N (64 cols)
    const int r    = lane >> 2;
    const int cq   = lane & 3;

    float acc[4][8][4];
#pragma unroll
    for (int i = 0; i < 4; i++)
#pragma unroll
        for (int j = 0; j < 8; j++)
#pragma unroll
            for (int q = 0; q < 4; q++) acc[i][j][q] = 0.f;

    // ---- ldmatrix per-lane geometry (bytes) ----
    const int T  = lane >> 3;
    const int ri = lane & 7;
    // A: row add (T&1)*8, k add (T>>1)*16B ; B: n add (T>>1)*8, k add (T&1)*16B
    const uint32_t sb = smem_u32(&smem[0][0]);
    const uint32_t aOff = (uint32_t)(wm * 64 + (T & 1) * 8 + ri) * PITCH + (uint32_t)(T >> 1) * 16;
    const uint32_t bOff = BOFFB + (uint32_t)(wn * 64 + (T >> 1) * 8 + ri) * PITCH + (uint32_t)(T & 1) * 16;

    // ---- loader geometry: 1 row per thread, 64B per tile ----
    const __half* aSrc = A + (size_t)(row0 + tid) * sAm;
    const int bRow = (col0 + tid < N) ? (col0 + tid) : (N - 1);
    const __half* bSrc = B + (size_t)bRow * sBn;
    const uint32_t aDst = sb + (uint32_t)tid * PITCH;
    const uint32_t bDst = sb + BOFFB + (uint32_t)tid * PITCH;

    uint4 aS[4], bS[4];
    const int nt = K / BKH;

    // ---- load tile 0 ----
#pragma unroll
    for (int c = 0; c < 4; c++) aS[c] = *(const uint4*)(aSrc + 8 * c);
#pragma unroll
    for (int c = 0; c < 4; c++) bS[c] = *(const uint4*)(bSrc + 8 * c);
#pragma unroll
    for (int c = 0; c < 4; c++) *(uint4*)(smem[0] + (aDst - sb) + 16 * c) = aS[c];
#pragma unroll
    for (int c = 0; c < 4; c++) *(uint4*)(smem[0] + (bDst - sb) + 16 * c) = bS[c];
    __syncthreads();

    int cur = 0;
    for (int t = 0; t < nt; t++) {
        const bool nxt = (t + 1) < nt;
        if (nxt) {
            const int kn = (t + 1) * BKH;
#pragma unroll
            for (int c = 0; c < 4; c++) aS[c] = *(const uint4*)(aSrc + kn + 8 * c);
#pragma unroll
            for (int c = 0; c < 4; c++) bS[c] = *(const uint4*)(bSrc + kn + 8 * c);
        }

        // ---- compute tile from buffer `cur` : 2 k16 steps ----
        const uint32_t aB = sb + (uint32_t)cur * (2 * BOFFB) + aOff;
        const uint32_t bB = sb + (uint32_t)cur * (2 * BOFFB) + bOff;
#pragma unroll
        for (int s = 0; s < 2; s++) {
            uint32_t af[4][4];
            uint32_t bf[8][2];
#pragma unroll
            for (int mt = 0; mt < 4; mt++)
                ldsm4(af[mt][0], af[mt][1], af[mt][2], af[mt][3],
                      aB + (uint32_t)s * 32 + (uint32_t)mt * (16 * PITCH));
#pragma unroll
            for (int p = 0; p < 4; p++)
                ldsm4(bf[2 * p][0], bf[2 * p][1], bf[2 * p + 1][0], bf[2 * p + 1][1],
                      bB + (uint32_t)s * 32 + (uint32_t)p * (16 * PITCH));
#pragma unroll
            for (int mt = 0; mt < 4; mt++)
#pragma unroll
                for (int nt8 = 0; nt8 < 8; nt8++)
                    mma_f16(acc[mt][nt8], af[mt], bf[nt8]);
        }

        if (nxt) {
            const int nb = cur ^ 1;
            uint8_t* base = smem[nb];
#pragma unroll
            for (int c = 0; c < 4; c++) *(uint4*)(base + (aDst - sb) + 16 * c) = aS[c];
#pragma unroll
            for (int c = 0; c < 4; c++) *(uint4*)(base + (bDst - sb) + 16 * c) = bS[c];
            cur = nb;
            __syncthreads();
        }
    }

    // ---- epilogue ----
#pragma unroll
    for (int mt = 0; mt < 4; mt++) {
        const int rr0 = row0 + wm * 64 + mt * 16 + r;
        const int rr1 = rr0 + 8;
#pragma unroll
        for (int nt8 = 0; nt8 < 8; nt8++) {
            const int cc0 = col0 + wn * 64 + nt8 * 8 + 2 * cq;
            const int cc1 = cc0 + 1;
#pragma unroll
            for (int e = 0; e < 2; e++) {
                const int cc = e ? cc1 : cc0;
                if (cc >= N) continue;
                float v0 = acc[mt][nt8][e]     * alpha;
                float v1 = acc[mt][nt8][e + 2] * alpha;
                if (bias) { float bv = bias[cc]; v0 += bv; v1 += bv; }
                if (relu) { v0 = fmaxf(v0, 0.f); v1 = fmaxf(v1, 0.f); }
                if (cHalf) {
                    Ch[(size_t)rr0 * sCm + cc] = __float2half_rn(v0);
                    Ch[(size_t)rr1 * sCm + cc] = __float2half_rn(v1);
                } else {
                    Cf[(size_t)rr0 * sCm + cc] = v0;
                    Cf[(size_t)rr1 * sCm + cc] = v1;
                }
            }
        }
    }
}

// ---------------- prep: f32 -> f16 copy --------------------------------------
__global__ __launch_bounds__(256)
void conv_h(const float* __restrict__ in, __half* __restrict__ out, int n)
{
    const int i = (blockIdx.x * 256 + threadIdx.x) * 4;
    if (i < n) {
        float4 v = *(const float4*)(in + i);
        __half2* o = (__half2*)(out + i);
        o[0] = __floats2half2_rn(v.x, v.y);
        o[1] = __floats2half2_rn(v.z, v.w);
    }
}

// ---------------- prep: f32 [R,C] -> f16 [C,R] transpose --------------------
__global__ void transpose_h(const float* __restrict__ in, __half* __restrict__ out,
                            int R, int Cc)
{
    __shared__ float t[32][33];
    const size_t bi = (size_t)blockIdx.z * R * Cc;
    const int r0 = blockIdx.y * 32, c0 = blockIdx.x * 32;
    const int tx = threadIdx.x, ty = threadIdx.y;
#pragma unroll
    for (int i = 0; i < 4; i++)
        t[ty + 8 * i][tx] = in[bi + (size_t)(r0 + ty + 8 * i) * Cc + c0 + tx];
    __syncthreads();
#pragma unroll
    for (int i = 0; i < 4; i++)
        out[bi + (size_t)(c0 + ty + 8 * i) * R + r0 + tx] = __float2half_rn(t[tx][ty + 8 * i]);
}

// ---------------- softmax over rows of 1024 halfs ----------------------------
__global__ __launch_bounds__(256)
void softmax_h(__half* __restrict__ S)
{
    __half2* p = (__half2*)(S + (size_t)blockIdx.x * 1024);
    const int t = threadIdx.x;
    const int lane = t & 31, wid = t >> 5;
    __shared__ float red[8];

    float2 a = __half22float2(p[2 * t]);
    float2 b = __half22float2(p[2 * t + 1]);
    float m = fmaxf(fmaxf(a.x, a.y), fmaxf(b.x, b.y));
#pragma unroll
    for (int s = 16; s > 0; s >>= 1) m = fmaxf(m, __shfl_xor_sync(0xffffffffu, m, s));
    if (lane == 0) red[wid] = m;
    __syncthreads();
    m = red[lane & 7];
#pragma unroll
    for (int s = 4; s > 0; s >>= 1) m = fmaxf(m, __shfl_xor_sync(0xffffffffu, m, s));
    m = __shfl_sync(0xffffffffu, m, 0);

    a.x = __expf(a.x - m); a.y = __expf(a.y - m);
    b.x = __expf(b.x - m); b.y = __expf(b.y - m);
    float sum = a.x + a.y + b.x + b.y;
#pragma unroll
    for (int s = 16; s > 0; s >>= 1) sum += __shfl_xor_sync(0xffffffffu, sum, s);
    __syncthreads();
    if (lane == 0) red[wid] = sum;
    __syncthreads();
    sum = red[lane & 7];
#pragma unroll
    for (int s = 4; s > 0; s >>= 1) sum += __shfl_xor_sync(0xffffffffu, sum, s);
    sum = __shfl_sync(0xffffffffu, sum, 0);

    const float inv = 1.f / sum;
    p[2 * t]     = __floats2half2_rn(a.x * inv, a.y * inv);
    p[2 * t + 1] = __floats2half2_rn(b.x * inv, b.y * inv);
}

// ---------------- residual + layernorm (rows of 512) ------------------------
__global__ __launch_bounds__(256)
void ln_k(float* __restrict__ out, __half* __restrict__ outh,
          const float* __restrict__ a, const float* __restrict__ b,
          const float* __restrict__ gamma, const float* __restrict__ beta)
{
    size_t base = (size_t)blockIdx.x * DD;
    int t = threadIdx.x;
    float x0 = a[base + t]       + b[base + t];
    float x1 = a[base + t + 256] + b[base + t + 256];

    __shared__ float r1[256], r2[256];
    r1[t] = x0 + x1;
    r2[t] = x0 * x0 + x1 * x1;
    __syncthreads();
    for (int s = 128; s > 0; s >>= 1) {
        if (t < s) { r1[t] += r1[t + s]; r2[t] += r2[t + s]; }
        __syncthreads();
    }
    float mean = r1[0] * (1.f / DD);
    float var  = r2[0] * (1.f / DD) - mean * mean;
    float rstd = rsqrtf(var + LN_EPS);

    float y0 = gamma[t]       * (x0 - mean) * rstd + beta[t];
    float y1 = gamma[t + 256] * (x1 - mean) * rstd + beta[t + 256];
    out[base + t]       = y0;
    out[base + t + 256] = y1;
    if (outh) {
        outh[base + t]       = __float2half_rn(y0);
        outh[base + t + 256] = __float2half_rn(y1);
    }
}

// ---------------- host side --------------------------------------------------
static void gemm(const __half* A, const __half* B, void* C, int cHalf, const float* bias,
                 int M, int N, int K, int sAm, int sBn, int sCm,
                 int nb, int HD, long long sA1, long long sA2, long long sB1, long long sB2,
                 long long sC1, long long sC2, float alpha, int relu)
{
    dim3 grid((N + BN - 1) / BN, M / BM, nb);
    gemm_h<<<grid, 128>>>(A, B, C, cHalf, bias, M, N, K, sAm, sBn, sCm,
                          HD, sA1, sA2, sB1, sB2, sC1, sC2, alpha, relu);
}

extern "C" void kernel_launch(void* const* d_in, const int* in_sizes, int n_in,
                              void* d_out, int out_size)
{
    const float* x      = (const float*)d_in[0];
    const float* qw     = (const float*)d_in[1];
    const float* kw     = (const float*)d_in[2];
    const float* vw     = (const float*)d_in[3];
    const float* lw     = (const float*)d_in[4];
    const float* gamma1 = (const float*)d_in[5];
    const float* beta1  = (const float*)d_in[6];
    const float* w1     = (const float*)d_in[7];
    const float* b1     = (const float*)d_in[8];
    const float* w2     = (const float*)d_in[9];
    const float* b2     = (const float*)d_in[10];
    const float* gamma2 = (const float*)d_in[11];
    const float* beta2  = (const float*)d_in[12];
    float* out = (float*)d_out;

    __half *xh, *qwT, *kwT, *vwT, *lwT, *w1T, *w2T;
    __half *qh, *kh, *vh, *sch, *cth, *hh, *ffh;
    float *tmp, *h;
    cudaGetSymbolAddress((void**)&xh,  g_xh);
    cudaGetSymbolAddress((void**)&qwT, g_qwT);
    cudaGetSymbolAddress((void**)&kwT, g_kwT);
    cudaGetSymbolAddress((void**)&vwT, g_vwT);
    cudaGetSymbolAddress((void**)&lwT, g_lwT);
    cudaGetSymbolAddress((void**)&w1T, g_w1T);
    cudaGetSymbolAddress((void**)&w2T, g_w2T);
    cudaGetSymbolAddress((void**)&qh,  g_qh);
    cudaGetSymbolAddress((void**)&kh,  g_kh);
    cudaGetSymbolAddress((void**)&vh,  g_vh);
    cudaGetSymbolAddress((void**)&sch, g_sch);
    cudaGetSymbolAddress((void**)&cth, g_cth);
    cudaGetSymbolAddress((void**)&hh,  g_hh);
    cudaGetSymbolAddress((void**)&ffh, g_ffh);
    cudaGetSymbolAddress((void**)&tmp, g_tmp);
    cudaGetSymbolAddress((void**)&h,   g_h);

    // ---- prep: convert / transpose to half, K-major ----
    conv_h<<<(BB * SS * DD / 4 + 255) / 256, 256>>>(x, xh, BB * SS * DD);
    transpose_h<<<dim3(2, 16, 8),   dim3(32, 8)>>>(qw, qwT, DD, UU);
    transpose_h<<<dim3(2, 16, 8),   dim3(32, 8)>>>(kw, kwT, DD, UU);
    transpose_h<<<dim3(16, 16, 8),  dim3(32, 8)>>>(vw, vwT, DD, DD);
    transpose_h<<<dim3(16, 128, 1), dim3(32, 8)>>>(lw, lwT, HH * DD, DD);
    transpose_h<<<dim3(64, 16, 1),  dim3(32, 8)>>>(w1, w1T, DD, FF);
    transpose_h<<<dim3(16, 64, 1),  dim3(32, 8)>>>(w2, w2T, FF, DD);

    // z = head*BB + batch (HD = BB)
    // 1) Q[z][s][u] = sum_d xh[b][s][d] * qwT[h][u][d]
    gemm(xh, qwT, qh, 1, nullptr, SS, UU, DD, DD, DD, UU,
         HH * BB, BB, 0LL, (long long)SS * DD, (long long)UU * DD, 0LL,
         (long long)BB * SS * UU, (long long)SS * UU, 1.f, 0);

    // 2) K likewise
    gemm(xh, kwT, kh, 1, nullptr, SS, UU, DD, DD, DD, UU,
         HH * BB, BB, 0LL, (long long)SS * DD, (long long)UU * DD, 0LL,
         (long long)BB * SS * UU, (long long)SS * UU, 1.f, 0);

    // 3) V^T[z][e][s] = sum_d vwT[h][e][d] * xh[b][s][d]
    gemm(vwT, xh, vh, 1, nullptr, DD, SS, DD, DD, DD, SS,
         HH * BB, BB, (long long)DD * DD, 0LL, 0LL, (long long)SS * DD,
         (long long)BB * DD * SS, (long long)DD * SS, 1.f, 0);

    // 4) scores[z][s][t] = SCALE * sum_u Q K   (K=64)
    gemm(qh, kh, sch, 1, nullptr, SS, SS, UU, UU, UU, SS,
         HH * BB, HH * BB, 0LL, (long long)SS * UU, 0LL, (long long)SS * UU,
         0LL, (long long)SS * SS, SCALE, 0);

    // 5) softmax rows (half in/out)
    softmax_h<<<HH * BB * SS, 256>>>(sch);

    // 6) attn[z][s][e] = sum_t P V^T -> concat [B,S,H*D] (half)
    gemm(sch, vh, cth, 1, nullptr, SS, DD, SS, SS, SS, HH * DD,
         HH * BB, BB, (long long)BB * SS * SS, (long long)SS * SS,
         (long long)BB * DD * SS, (long long)DD * SS,
         (long long)DD, (long long)SS * HH * DD, 1.f, 0);

    // 7) output projection -> tmp (f32), K=4096
    gemm(cth, lwT, tmp, 0, nullptr, BB * SS, DD, HH * DD, HH * DD, HH * DD, DD,
         1, 1, 0LL, 0LL, 0LL, 0LL, 0LL, 0LL, 1.f, 0);

    // 8) h = LN(x + mha), hh = half(h)
    ln_k<<<BB * SS, 256>>>(h, hh, x, tmp, gamma1, beta1);

    // 9) ff = relu(hh @ w1 + b1) -> half
    gemm(hh, w1T, ffh, 1, b1, BB * SS, FF, DD, DD, DD, FF,
         1, 1, 0LL, 0LL, 0LL, 0LL, 0LL, 0LL, 1.f, 1);

    // 10) tmp = ff @ w2 + b2 -> f32
    gemm(ffh, w2T, tmp, 0, b2, BB * SS, DD, FF, FF, FF, DD,
         1, 1, 0LL, 0LL, 0LL, 0LL, 0LL, 0LL, 1.f, 0);

    // 11) out = LN(h + tmp)
    ln_k<<<BB * SS, 256>>>(out, nullptr, h, tmp, gamma2, beta2);
}